// round 13
// baseline (speedup 1.0000x reference)
#include <cuda_runtime.h>
#include <cuda_fp16.h>
#include <math.h>

#define NB 256
#define NJ 10
#define NI 1152
#define NP 16
#define NQ 8
#define NICH 18         // i-chunks for k_hat (64 i each)
#define NCH 18          // i-chunks for route (64 i each)
#define CH 64           // i per route chunk
#define JP (NJ * NP)    // 160
#define CBS 72          // cbuf stride (64 + 8 pad)
#define JST 520         // uint words per j-block in smem hat (512 + 8 pad)

// Scratch (device globals — no allocation anywhere).
__device__ __half g_hat[(size_t)NB * NJ * NI * NP];     // [b][j][i][p], 94.4 MB
__device__ float  g_s0part[NICH * NB * JP];             // [ic][b][j*16+p]
__device__ float  g_spartB[NB * NCH * JP];              // pass-B partials
__device__ float  g_spartC[NB * NCH * JP];              // pass-C partials

// ---------------------------------------------------------------------------
// K1: hat[b,j,i,p] = sum_q W[j,i,p,q]*in[b,i,q] in half2 (HFMA2), fp16 store.
// R7 geometry (grid (18,10,4), 64 b per block, natural regs).
// s0 reduction: 1-round butterfly (d=4) -> 16 writer lanes -> 32 SMEM slots
// -> deterministic flush.
// ---------------------------------------------------------------------------
__global__ __launch_bounds__(256) void k_hat(const float* __restrict__ in,
                                             const float* __restrict__ W) {
    const int ic = blockIdx.x;
    const int j  = blockIdx.y;
    const int bc = blockIdx.z;          // 0..3 (64 b each)
    const int t  = threadIdx.x;
    const int p4 = t & 3;
    const int il = t >> 2;
    const int i  = ic * 64 + il;
    const int lane = t & 31;
    const int wrp  = t >> 5;

    __half2 w01[8], w23[8];
    {
        float w[4][8];
        const float4* Wv = (const float4*)(W + ((size_t)(j * NI + i) * NP + p4 * 4) * NQ);
        #pragma unroll
        for (int pp = 0; pp < 4; pp++) {
            float4 a = Wv[pp * 2], c = Wv[pp * 2 + 1];
            w[pp][0] = a.x; w[pp][1] = a.y; w[pp][2] = a.z; w[pp][3] = a.w;
            w[pp][4] = c.x; w[pp][5] = c.y; w[pp][6] = c.z; w[pp][7] = c.w;
        }
        #pragma unroll
        for (int q = 0; q < 8; q++) {
            w01[q] = __floats2half2_rn(w[0][q], w[1][q]);
            w23[q] = __floats2half2_rn(w[2][q], w[3][q]);
        }
    }

    __shared__ __align__(16) uint4 in_s[8 * 64 * 2];   // dup half2 packed, 16 KB
    __shared__ float s0w[32 * 128];                    // [wrp*4+k][bb*16+p], 16 KB

    // 1-round butterfly: after XOR-4, lanes with (lane&4)==0 hold il-pair
    // sums; k = (lane>>3) indexes the pair within this warp's il-octet.
    const bool s0wr = (lane & 4) == 0;
    const int  s0slot = (wrp * 4 + (lane >> 3)) * 128 + (lane & 3) * 4;

    for (int g = 0; g < 8; g++) {
        const int b0 = bc * 64 + g * 8;
        __syncthreads();                  // in_s + s0w reuse safe
        #pragma unroll
        for (int k = 0; k < 4; k++) {
            int m   = t + 256 * k;        // float4 index 0..1023
            int bo  = m >> 7;             // 128 float4 per b
            int pos = m & 127;
            float4 v = ((const float4*)(in + ((size_t)(b0 + bo) * NI + ic * 64) * NQ))[pos];
            union { __half2 h[4]; uint4 u; } pk;
            pk.h[0] = __floats2half2_rn(v.x, v.x);
            pk.h[1] = __floats2half2_rn(v.y, v.y);
            pk.h[2] = __floats2half2_rn(v.z, v.z);
            pk.h[3] = __floats2half2_rn(v.w, v.w);
            in_s[bo * 128 + pos] = pk.u;   // STS.128
        }
        __syncthreads();
        #pragma unroll
        for (int bb = 0; bb < 8; bb++) {
            const int b = b0 + bb;
            union { uint4 u; __half2 h[4]; } xa, xb;
            xa.u = in_s[(bb * 64 + il) * 2 + 0];   // LDS.128
            xb.u = in_s[(bb * 64 + il) * 2 + 1];   // LDS.128

            __half2 c0 = __hmul2(xa.h[0], w01[0]);
            c0 = __hfma2(xa.h[1], w01[1], c0);
            c0 = __hfma2(xa.h[2], w01[2], c0);
            c0 = __hfma2(xa.h[3], w01[3], c0);
            __half2 c1 = __hmul2(xb.h[0], w01[4]);
            c1 = __hfma2(xb.h[1], w01[5], c1);
            c1 = __hfma2(xb.h[2], w01[6], c1);
            c1 = __hfma2(xb.h[3], w01[7], c1);
            __half2 r01 = __hadd2(c0, c1);

            __half2 d0 = __hmul2(xa.h[0], w23[0]);
            d0 = __hfma2(xa.h[1], w23[1], d0);
            d0 = __hfma2(xa.h[2], w23[2], d0);
            d0 = __hfma2(xa.h[3], w23[3], d0);
            __half2 d1 = __hmul2(xb.h[0], w23[4]);
            d1 = __hfma2(xb.h[1], w23[5], d1);
            d1 = __hfma2(xb.h[2], w23[6], d1);
            d1 = __hfma2(xb.h[3], w23[7], d1);
            __half2 r23 = __hadd2(d0, d1);

            union { __half2 h2[2]; uint2 u; } pk;
            pk.h2[0] = r01; pk.h2[1] = r23;
            *(uint2*)(g_hat + ((size_t)(b * NJ + j) * NI + i) * NP + p4 * 4) = pk.u;

            // single butterfly round (d=4)
            union { __half2 h; unsigned int u; } s01, s23;
            s01.h = r01; s23.h = r23;
            {
                union { __half2 h; unsigned int u; } o1, o2;
                o1.u = __shfl_xor_sync(0xffffffffu, s01.u, 4);
                o2.u = __shfl_xor_sync(0xffffffffu, s23.u, 4);
                s01.h = __hadd2(s01.h, o1.h);
                s23.h = __hadd2(s23.h, o2.h);
            }
            if (s0wr) {
                float2 f01 = __half22float2(s01.h);
                float2 f23 = __half22float2(s23.h);
                float4 v; v.x = f01.x; v.y = f01.y; v.z = f23.x; v.w = f23.y;
                *(float4*)(&s0w[s0slot + bb * 16]) = v;
            }
        }
        __syncthreads();                     // s0w complete
        if (t < 128) {                       // deterministic flush, no atomics
            int bb2 = t >> 4, p = t & 15;
            float a = 0.f;
            #pragma unroll
            for (int w32 = 0; w32 < 32; w32++) a += s0w[w32 * 128 + t];
            g_s0part[(ic * NB + b0 + bb2) * JP + j * NP + p] = a;
        }
    }
}

// ---------------------------------------------------------------------------
// K2/K3: one routing pass, CH=64 chunks -> ~24 KB SMEM -> 8 blocks/SM.
// Head: routing vector. Phase 1: load+stage chunk, half2 dot -> logits.
// Phase 2: softmax (64 i). Phase 3: 80 threads (j, p-pair), direct write.
// grid (ic=18, b=256), block 256.
// ---------------------------------------------------------------------------
__global__ __launch_bounds__(256) void k_route(const float* __restrict__ spart_in,
                                               float* __restrict__ spart_out,
                                               int pass) {
    const int ic = blockIdx.x;
    const int b  = blockIdx.y;
    const int t  = threadIdx.x;

    __shared__ __align__(16) unsigned int smh[NJ * JST];  // hat chunk, 20.8 KB
    __shared__ float   cbuf[NJ * CBS];                    // 2.9 KB
    __shared__ float   ov[JP];
    __shared__ __align__(16) __half2 ovh[JP / 2];

    if (t < JP) {
        float s = 0.f;
        #pragma unroll
        for (int c2 = 0; c2 < NICH; c2++) s += g_s0part[(c2 * NB + b) * JP + t];
        s *= 0.1f;                             // c0 = 1/J exactly
        float sq = s * s;
        sq += __shfl_xor_sync(0xffffffffu, sq, 1);
        sq += __shfl_xor_sync(0xffffffffu, sq, 2);
        sq += __shfl_xor_sync(0xffffffffu, sq, 4);
        sq += __shfl_xor_sync(0xffffffffu, sq, 8);
        float sc = sq / ((1.f + sq) * sqrtf(sq + 1e-7f));
        float v = s * sc;                      // out0
        if (pass) {
            float s1 = 0.f;
            #pragma unroll
            for (int c2 = 0; c2 < NCH; c2++)
                s1 += spart_in[(b * NCH + c2) * JP + t];
            float q = s1 * s1;
            q += __shfl_xor_sync(0xffffffffu, q, 1);
            q += __shfl_xor_sync(0xffffffffu, q, 2);
            q += __shfl_xor_sync(0xffffffffu, q, 4);
            q += __shfl_xor_sync(0xffffffffu, q, 8);
            float sc1 = q / ((1.f + q) * sqrtf(q + 1e-7f));
            v += s1 * sc1;                     // out0 + out1
        }
        ov[t] = v;
    }
    __syncthreads();
    if (t < JP / 2) ovh[t] = __floats2half2_rn(ov[2 * t], ov[2 * t + 1]);
    __syncthreads();

    const __half* hb = g_hat + (size_t)b * NJ * NI * NP;
    const int i0 = ic * CH;

    // Phase 1: 640 rows, 256 threads: 2 full iters + partial.
    #pragma unroll
    for (int k = 0; k < 3; k++) {
        int idx = t + 256 * k;          // 0..639
        if (k < 2 || idx < 640) {
            int j = idx >> 6, il = idx & 63;
            const __half* h = hb + (size_t)(j * NI + i0 + il) * NP;
            union { uint4 u; __half2 h2[4]; } a, c, va, vb;
            a.u = ((const uint4*)h)[0];
            c.u = ((const uint4*)h)[1];
            const uint4* avv = (const uint4*)(ovh + j * 8);
            va.u = avv[0];                  // LDS.128
            vb.u = avv[1];                  // LDS.128
            __half2 acc0 = __hmul2(a.h2[0], va.h2[0]);
            acc0 = __hfma2(a.h2[1], va.h2[1], acc0);
            acc0 = __hfma2(a.h2[2], va.h2[2], acc0);
            acc0 = __hfma2(a.h2[3], va.h2[3], acc0);
            __half2 acc1 = __hmul2(c.h2[0], vb.h2[0]);
            acc1 = __hfma2(c.h2[1], vb.h2[1], acc1);
            acc1 = __hfma2(c.h2[2], vb.h2[2], acc1);
            acc1 = __hfma2(c.h2[3], vb.h2[3], acc1);
            float2 f = __half22float2(__hadd2(acc0, acc1));
            cbuf[j * CBS + il] = f.x + f.y;
            uint4* dst = (uint4*)(smh + j * JST + il * 8);
            dst[0] = a.u;
            dst[1] = c.u;
        }
    }
    __syncthreads();

    // Phase 2: softmax over j per i (64 i)
    if (t < CH) {
        float v[NJ];
        float mx = -1e30f;
        #pragma unroll
        for (int j = 0; j < NJ; j++) { v[j] = cbuf[j * CBS + t]; mx = fmaxf(mx, v[j]); }
        float sum = 0.f;
        #pragma unroll
        for (int j = 0; j < NJ; j++) { v[j] = __expf(v[j] - mx); sum += v[j]; }
        float inv = 1.f / sum;
        #pragma unroll
        for (int j = 0; j < NJ; j++) cbuf[j * CBS + t] = v[j] * inv;
    }
    __syncthreads();

    // Phase 3: 80 threads, thread = (j 0..9, p-pair 0..7); direct write.
    if (t < 80) {
        const int j = t >> 3, pj = t & 7;
        const __half2* hrow = (const __half2*)(smh + j * JST) + pj;  // 8 half2 per il
        const float* cc = cbuf + j * CBS;
        float ax = 0.f, ay = 0.f, bx = 0.f, by = 0.f;
        #pragma unroll
        for (int il = 0; il < CH; il += 2) {
            float2 f0 = __half22float2(hrow[(il + 0) * 8]);
            float2 f1 = __half22float2(hrow[(il + 1) * 8]);
            float c0 = cc[il], c1 = cc[il + 1];
            ax = fmaf(f0.x, c0, ax);
            ay = fmaf(f0.y, c0, ay);
            bx = fmaf(f1.x, c1, bx);
            by = fmaf(f1.y, c1, by);
        }
        float2 r; r.x = ax + bx; r.y = ay + by;
        ((float2*)(spart_out + (b * NCH + ic) * JP))[t] = r;   // floats [0,160)
    }
}

// ---------------------------------------------------------------------------
// K4: final = squash(sum of pass-C partials) -> d_out.
// ---------------------------------------------------------------------------
__global__ __launch_bounds__(160) void k_final(float* __restrict__ out) {
    const int b = blockIdx.x, t = threadIdx.x;
    float acc = 0.f;
    #pragma unroll
    for (int c2 = 0; c2 < NCH; c2++) acc += g_spartC[(b * NCH + c2) * JP + t];
    float sq = acc * acc;
    sq += __shfl_xor_sync(0xffffffffu, sq, 1);
    sq += __shfl_xor_sync(0xffffffffu, sq, 2);
    sq += __shfl_xor_sync(0xffffffffu, sq, 4);
    sq += __shfl_xor_sync(0xffffffffu, sq, 8);
    float sc = sq / ((1.f + sq) * sqrtf(sq + 1e-7f));
    out[b * JP + t] = acc * sc;
}

extern "C" void kernel_launch(void* const* d_in, const int* in_sizes, int n_in,
                              void* d_out, int out_size) {
    const float* in = (const float*)d_in[0];   // [256,1152,8]
    const float* W  = (const float*)d_in[1];   // [10,1152,16,8]
    float* out = (float*)d_out;                // [256,10,16]

    void* pB = nullptr; cudaGetSymbolAddress(&pB, g_spartB);
    void* pC = nullptr; cudaGetSymbolAddress(&pC, g_spartC);

    k_hat<<<dim3(NICH, NJ, 4), 256>>>(in, W);
    k_route<<<dim3(NCH, NB), 256>>>((const float*)pB, (float*)pB, 0);  // pass B
    k_route<<<dim3(NCH, NB), 256>>>((const float*)pB, (float*)pC, 1);  // pass C
    k_final<<<NB, 160>>>(out);
}

// round 14
// speedup vs baseline: 1.0836x; 1.0836x over previous
#include <cuda_runtime.h>
#include <cuda_fp16.h>
#include <math.h>

#define NB 256
#define NJ 10
#define NI 1152
#define NP 16
#define NQ 8
#define NICH 18         // i-chunks for k_hat (64 i each)
#define NCH 9           // i-chunks for route (128 i each)
#define CH 128          // i per route chunk
#define JP (NJ * NP)    // 160
#define CBS 136         // cbuf stride (128 + 8 pad)
#define JST 1032        // uint words per j-block in smem hat (1024 + 8 pad)

// Scratch (device globals — no allocation anywhere).
__device__ __half g_hat[(size_t)NB * NJ * NI * NP];     // [b][j][i][p], 94.4 MB
__device__ float  g_s0part[NICH * NB * JP];             // [ic][b][j*16+p]
__device__ float  g_spartB[NB * NCH * JP];              // pass-B partials
__device__ float  g_spartC[NB * NCH * JP];              // pass-C partials

// ---------------------------------------------------------------------------
// K1: hat[b,j,i,p] = sum_q W[j,i,p,q]*in[b,i,q] in half2 (HFMA2), fp16 store.
// R7 geometry (grid (18,10,4), 64 b per block, natural regs).
// s0 reduction: 1-round butterfly (d=4) -> 16 writer lanes -> 32 SMEM slots
// -> deterministic flush. (Verified correct in R13.)
// ---------------------------------------------------------------------------
__global__ __launch_bounds__(256) void k_hat(const float* __restrict__ in,
                                             const float* __restrict__ W) {
    const int ic = blockIdx.x;
    const int j  = blockIdx.y;
    const int bc = blockIdx.z;          // 0..3 (64 b each)
    const int t  = threadIdx.x;
    const int p4 = t & 3;
    const int il = t >> 2;
    const int i  = ic * 64 + il;
    const int lane = t & 31;
    const int wrp  = t >> 5;

    __half2 w01[8], w23[8];
    {
        float w[4][8];
        const float4* Wv = (const float4*)(W + ((size_t)(j * NI + i) * NP + p4 * 4) * NQ);
        #pragma unroll
        for (int pp = 0; pp < 4; pp++) {
            float4 a = Wv[pp * 2], c = Wv[pp * 2 + 1];
            w[pp][0] = a.x; w[pp][1] = a.y; w[pp][2] = a.z; w[pp][3] = a.w;
            w[pp][4] = c.x; w[pp][5] = c.y; w[pp][6] = c.z; w[pp][7] = c.w;
        }
        #pragma unroll
        for (int q = 0; q < 8; q++) {
            w01[q] = __floats2half2_rn(w[0][q], w[1][q]);
            w23[q] = __floats2half2_rn(w[2][q], w[3][q]);
        }
    }

    __shared__ __align__(16) uint4 in_s[8 * 64 * 2];   // dup half2 packed, 16 KB
    __shared__ float s0w[32 * 128];                    // [wrp*4+k][bb*16+p], 16 KB

    // 1-round butterfly: after XOR-4, lanes with (lane&4)==0 hold il-pair
    // sums; k = (lane>>3) indexes the pair within this warp's il-octet.
    const bool s0wr = (lane & 4) == 0;
    const int  s0slot = (wrp * 4 + (lane >> 3)) * 128 + (lane & 3) * 4;

    for (int g = 0; g < 8; g++) {
        const int b0 = bc * 64 + g * 8;
        __syncthreads();                  // in_s + s0w reuse safe
        #pragma unroll
        for (int k = 0; k < 4; k++) {
            int m   = t + 256 * k;        // float4 index 0..1023
            int bo  = m >> 7;             // 128 float4 per b
            int pos = m & 127;
            float4 v = ((const float4*)(in + ((size_t)(b0 + bo) * NI + ic * 64) * NQ))[pos];
            union { __half2 h[4]; uint4 u; } pk;
            pk.h[0] = __floats2half2_rn(v.x, v.x);
            pk.h[1] = __floats2half2_rn(v.y, v.y);
            pk.h[2] = __floats2half2_rn(v.z, v.z);
            pk.h[3] = __floats2half2_rn(v.w, v.w);
            in_s[bo * 128 + pos] = pk.u;   // STS.128
        }
        __syncthreads();
        #pragma unroll
        for (int bb = 0; bb < 8; bb++) {
            const int b = b0 + bb;
            union { uint4 u; __half2 h[4]; } xa, xb;
            xa.u = in_s[(bb * 64 + il) * 2 + 0];   // LDS.128
            xb.u = in_s[(bb * 64 + il) * 2 + 1];   // LDS.128

            __half2 c0 = __hmul2(xa.h[0], w01[0]);
            c0 = __hfma2(xa.h[1], w01[1], c0);
            c0 = __hfma2(xa.h[2], w01[2], c0);
            c0 = __hfma2(xa.h[3], w01[3], c0);
            __half2 c1 = __hmul2(xb.h[0], w01[4]);
            c1 = __hfma2(xb.h[1], w01[5], c1);
            c1 = __hfma2(xb.h[2], w01[6], c1);
            c1 = __hfma2(xb.h[3], w01[7], c1);
            __half2 r01 = __hadd2(c0, c1);

            __half2 d0 = __hmul2(xa.h[0], w23[0]);
            d0 = __hfma2(xa.h[1], w23[1], d0);
            d0 = __hfma2(xa.h[2], w23[2], d0);
            d0 = __hfma2(xa.h[3], w23[3], d0);
            __half2 d1 = __hmul2(xb.h[0], w23[4]);
            d1 = __hfma2(xb.h[1], w23[5], d1);
            d1 = __hfma2(xb.h[2], w23[6], d1);
            d1 = __hfma2(xb.h[3], w23[7], d1);
            __half2 r23 = __hadd2(d0, d1);

            union { __half2 h2[2]; uint2 u; } pk;
            pk.h2[0] = r01; pk.h2[1] = r23;
            *(uint2*)(g_hat + ((size_t)(b * NJ + j) * NI + i) * NP + p4 * 4) = pk.u;

            // single butterfly round (d=4): sum il with il^1
            union { __half2 h; unsigned int u; } s01, s23;
            s01.h = r01; s23.h = r23;
            {
                union { __half2 h; unsigned int u; } o1, o2;
                o1.u = __shfl_xor_sync(0xffffffffu, s01.u, 4);
                o2.u = __shfl_xor_sync(0xffffffffu, s23.u, 4);
                s01.h = __hadd2(s01.h, o1.h);
                s23.h = __hadd2(s23.h, o2.h);
            }
            if (s0wr) {
                float2 f01 = __half22float2(s01.h);
                float2 f23 = __half22float2(s23.h);
                float4 v; v.x = f01.x; v.y = f01.y; v.z = f23.x; v.w = f23.y;
                *(float4*)(&s0w[s0slot + bb * 16]) = v;
            }
        }
        __syncthreads();                     // s0w complete
        if (t < 128) {                       // deterministic flush, no atomics
            int bb2 = t >> 4, p = t & 15;
            float a = 0.f;
            #pragma unroll
            for (int w32 = 0; w32 < 32; w32++) a += s0w[w32 * 128 + t];
            g_s0part[(ic * NB + b0 + bb2) * JP + j * NP + p] = a;
        }
    }
}

// ---------------------------------------------------------------------------
// K2/K3: one routing pass (R11-exact). Head: routing vector. Phase 1:
// load+stage hat chunk, half2 dot -> logits. Phase 2: softmax. Phase 3:
// p-pair threads, half2 loads, il-split 2x80. grid (ic=9, b=256), block 256.
// ---------------------------------------------------------------------------
__global__ __launch_bounds__(256) void k_route(const float* __restrict__ spart_in,
                                               float* __restrict__ spart_out,
                                               int pass) {
    const int ic = blockIdx.x;
    const int b  = blockIdx.y;
    const int t  = threadIdx.x;

    __shared__ __align__(16) unsigned int smh[NJ * JST];  // hat chunk, 41.3 KB
    __shared__ float   cbuf[NJ * CBS];
    __shared__ float   ov[JP];
    __shared__ __align__(16) __half2 ovh[JP / 2];
    __shared__ float2  p3buf[160];

    if (t < JP) {
        float s = 0.f;
        #pragma unroll
        for (int c2 = 0; c2 < NICH; c2++) s += g_s0part[(c2 * NB + b) * JP + t];
        s *= 0.1f;                             // c0 = 1/J exactly
        float sq = s * s;
        sq += __shfl_xor_sync(0xffffffffu, sq, 1);
        sq += __shfl_xor_sync(0xffffffffu, sq, 2);
        sq += __shfl_xor_sync(0xffffffffu, sq, 4);
        sq += __shfl_xor_sync(0xffffffffu, sq, 8);
        float sc = sq / ((1.f + sq) * sqrtf(sq + 1e-7f));
        float v = s * sc;                      // out0
        if (pass) {
            float s1 = 0.f;
            #pragma unroll
            for (int c2 = 0; c2 < NCH; c2++)
                s1 += spart_in[(b * NCH + c2) * JP + t];
            float q = s1 * s1;
            q += __shfl_xor_sync(0xffffffffu, q, 1);
            q += __shfl_xor_sync(0xffffffffu, q, 2);
            q += __shfl_xor_sync(0xffffffffu, q, 4);
            q += __shfl_xor_sync(0xffffffffu, q, 8);
            float sc1 = q / ((1.f + q) * sqrtf(q + 1e-7f));
            v += s1 * sc1;                     // out0 + out1
        }
        ov[t] = v;
    }
    __syncthreads();
    if (t < JP / 2) ovh[t] = __floats2half2_rn(ov[2 * t], ov[2 * t + 1]);
    __syncthreads();

    const __half* hb = g_hat + (size_t)b * NJ * NI * NP;
    const int i0 = ic * CH;

    // Phase 1: load + stage + logits (half2 dot, LDS.128 routing vector)
    #pragma unroll
    for (int k = 0; k < 5; k++) {
        int idx = t + 256 * k;          // 0..1279
        int j = idx >> 7, il = idx & 127;
        const __half* h = hb + (size_t)(j * NI + i0 + il) * NP;
        union { uint4 u; __half2 h2[4]; } a, c, va, vb;
        a.u = ((const uint4*)h)[0];
        c.u = ((const uint4*)h)[1];
        const uint4* avv = (const uint4*)(ovh + j * 8);
        va.u = avv[0];                  // LDS.128
        vb.u = avv[1];                  // LDS.128
        __half2 acc0 = __hmul2(a.h2[0], va.h2[0]);
        acc0 = __hfma2(a.h2[1], va.h2[1], acc0);
        acc0 = __hfma2(a.h2[2], va.h2[2], acc0);
        acc0 = __hfma2(a.h2[3], va.h2[3], acc0);
        __half2 acc1 = __hmul2(c.h2[0], vb.h2[0]);
        acc1 = __hfma2(c.h2[1], vb.h2[1], acc1);
        acc1 = __hfma2(c.h2[2], vb.h2[2], acc1);
        acc1 = __hfma2(c.h2[3], vb.h2[3], acc1);
        float2 f = __half22float2(__hadd2(acc0, acc1));
        cbuf[j * CBS + il] = f.x + f.y;
        uint4* dst = (uint4*)(smh + j * JST + il * 8);
        dst[0] = a.u;
        dst[1] = c.u;
    }
    __syncthreads();

    // Phase 2: softmax over j per i
    if (t < CH) {
        float v[NJ];
        float mx = -1e30f;
        #pragma unroll
        for (int j = 0; j < NJ; j++) { v[j] = cbuf[j * CBS + t]; mx = fmaxf(mx, v[j]); }
        float sum = 0.f;
        #pragma unroll
        for (int j = 0; j < NJ; j++) { v[j] = __expf(v[j] - mx); sum += v[j]; }
        float inv = 1.f / sum;
        #pragma unroll
        for (int j = 0; j < NJ; j++) cbuf[j * CBS + t] = v[j] * inv;
    }
    __syncthreads();

    // Phase 3: p-pair threads (t<160): grp = il-half, pp = (j, p-pair).
    if (t < 160) {
        const int grp = t / 80;          // il half: 0 or 1
        const int pp  = t % 80;
        const int j = pp >> 3, pj = pp & 7;
        const __half2* hrow = (const __half2*)(smh + j * JST) + pj;  // 8 half2 per il
        const float* cc = cbuf + j * CBS;
        const int il0 = grp * 64;
        float ax = 0.f, ay = 0.f, bx = 0.f, by = 0.f;
        #pragma unroll
        for (int il = il0; il < il0 + 64; il += 2) {
            float2 f0 = __half22float2(hrow[(il + 0) * 8]);
            float2 f1 = __half22float2(hrow[(il + 1) * 8]);
            float c0 = cc[il], c1 = cc[il + 1];
            ax = fmaf(f0.x, c0, ax);
            ay = fmaf(f0.y, c0, ay);
            bx = fmaf(f1.x, c1, bx);
            by = fmaf(f1.y, c1, by);
        }
        float2 r; r.x = ax + bx; r.y = ay + by;
        p3buf[t] = r;
    }
    __syncthreads();
    if (t < 80) {
        float2 r0 = p3buf[t], r1 = p3buf[t + 80];
        float2 r; r.x = r0.x + r1.x; r.y = r0.y + r1.y;
        *(float2*)(spart_out + (b * NCH + ic) * JP + t * 2) = r;
    }
}

// ---------------------------------------------------------------------------
// K4: final = squash(sum of pass-C partials) -> d_out.
// ---------------------------------------------------------------------------
__global__ __launch_bounds__(160) void k_final(float* __restrict__ out) {
    const int b = blockIdx.x, t = threadIdx.x;
    float acc = 0.f;
    #pragma unroll
    for (int c2 = 0; c2 < NCH; c2++) acc += g_spartC[(b * NCH + c2) * JP + t];
    float sq = acc * acc;
    sq += __shfl_xor_sync(0xffffffffu, sq, 1);
    sq += __shfl_xor_sync(0xffffffffu, sq, 2);
    sq += __shfl_xor_sync(0xffffffffu, sq, 4);
    sq += __shfl_xor_sync(0xffffffffu, sq, 8);
    float sc = sq / ((1.f + sq) * sqrtf(sq + 1e-7f));
    out[b * JP + t] = acc * sc;
}

extern "C" void kernel_launch(void* const* d_in, const int* in_sizes, int n_in,
                              void* d_out, int out_size) {
    const float* in = (const float*)d_in[0];   // [256,1152,8]
    const float* W  = (const float*)d_in[1];   // [10,1152,16,8]
    float* out = (float*)d_out;                // [256,10,16]

    void* pB = nullptr; cudaGetSymbolAddress(&pB, g_spartB);
    void* pC = nullptr; cudaGetSymbolAddress(&pC, g_spartC);

    k_hat<<<dim3(NICH, NJ, 4), 256>>>(in, W);
    k_route<<<dim3(NCH, NB), 256>>>((const float*)pB, (float*)pB, 0);  // pass B
    k_route<<<dim3(NCH, NB), 256>>>((const float*)pB, (float*)pC, 1);  // pass C
    k_final<<<NB, 160>>>(out);
}